// round 16
// baseline (speedup 1.0000x reference)
#include <cuda_runtime.h>
#include <cuda_fp16.h>
#include <cstdint>

#define B_DIM 16
#define L_DIM 2048
#define F_DIM 512

#define CTA_M 128
#define CTA_N 128
#define KC    32
#define NCH   (L_DIM / KC)   /* 64 */
#define NSTAGE 4
#define THREADS 128

__device__ __half g_featx[(size_t)B_DIM * L_DIM * F_DIM];  /* 32 MB */

/* stage = A fp32 128x32 (16KB, converted in place to fp16) + B fp16 32x128 (8KB) */
#define A_STAGE 16384
#define B_STAGE 8192
#define STAGE_BYTES (A_STAGE + B_STAGE)
#define SMEM_BYTES (NSTAGE * STAGE_BYTES)   /* 98304 per CTA -> 2 CTAs/SM */

/* ============== prepass: feature fp32 -> fp16 (32 MB) ============== */
__global__ void __launch_bounds__(256, 8)
prep_feat(const float* __restrict__ feat)
{
    const size_t i = (size_t)blockIdx.x * 256 + threadIdx.x;
    const float4 v = __ldcs(((const float4*)feat) + i);
    __half2 p0 = __floats2half2_rn(v.x, v.y);
    __half2 p1 = __floats2half2_rn(v.z, v.w);
    uint2 u;
    u.x = *(uint32_t*)&p0; u.y = *(uint32_t*)&p1;
    ((uint2*)g_featx)[i] = u;
}

/* ============== fused exp + fp16 GEMM ============== */
__device__ __forceinline__ void mma_f16(float* c, const uint32_t* a, const uint32_t* b) {
    asm volatile(
        "mma.sync.aligned.m16n8k16.row.col.f32.f16.f16.f32 "
        "{%0,%1,%2,%3}, {%4,%5,%6,%7}, {%8,%9}, {%0,%1,%2,%3};"
        : "+f"(c[0]), "+f"(c[1]), "+f"(c[2]), "+f"(c[3])
        : "r"(a[0]), "r"(a[1]), "r"(a[2]), "r"(a[3]), "r"(b[0]), "r"(b[1]));
}

#define LDSM4(R, ADDR)                                                        \
    asm volatile("ldmatrix.sync.aligned.m8n8.x4.shared.b16 {%0,%1,%2,%3},[%4];" \
                 : "=r"((R)[0]), "=r"((R)[1]), "=r"((R)[2]), "=r"((R)[3]) : "r"(ADDR))

#define LDSM4T(R0, R1, R2, R3, ADDR)                                          \
    asm volatile("ldmatrix.sync.aligned.m8n8.x4.trans.shared.b16 {%0,%1,%2,%3},[%4];" \
                 : "=r"(R0), "=r"(R1), "=r"(R2), "=r"(R3) : "r"(ADDR))

#define CPA16(SADDR, GPTR)                                                    \
    asm volatile("cp.async.cg.shared.global [%0], [%1], 16;"                  \
                 :: "r"(SADDR), "l"(GPTR))

__global__ void __launch_bounds__(THREADS, 2)
FrameAugment_39771397161402_kernel(const float* __restrict__ noise,
                                   float* __restrict__ out)
{
    extern __shared__ char smraw[];
    uint32_t sbase;
    asm("{ .reg .u64 t; cvta.to.shared.u64 t, %1; cvt.u32.u64 %0, t; }"
        : "=r"(sbase) : "l"(smraw));

    const int tid  = threadIdx.x;
    const int lane = tid & 31;
    const int w    = tid >> 5;
    const int q    = lane >> 2;
    const int qt   = lane & 3;
    const int wm   = w >> 1;      /* 0..1 : 64 rows */
    const int wn   = w & 1;       /* 0..1 : 64 cols */

    const int b  = blockIdx.z;
    const int m0 = blockIdx.x * CTA_M;
    const int n0 = blockIdx.y * CTA_N;

    const float*  aG = noise + ((size_t)b * L_DIM + m0) * L_DIM;
    const __half* bG = g_featx + (size_t)b * L_DIM * F_DIM + n0;
    float*        oG = out + ((size_t)b * L_DIM + m0) * F_DIM + n0;

    /* ---- A producer (fp32): 4 rows per CPA16 wave; thread: row tid>>3 (+16*k), chunk tid&7 ---- */
    const int arow = tid >> 3, ac = tid & 7;
    const int askew = ac ^ (arow & 7);                      /* constant per thread */
    const uint32_t aoff = (uint32_t)arow * 128u + ((uint32_t)askew << 4);
    const size_t   gaoff = (size_t)arow * L_DIM + ac * 4;

    /* ---- B producer: rows tid>>4 (+8,+16,+24), chunk tid&15 ---- */
    const int brow = tid >> 4, bc = tid & 15;
    const uint32_t boff = (uint32_t)brow * 256u +
                          (uint32_t)(((bc & 8) | ((bc & 7) ^ (brow & 7))) << 4);
    const size_t   gboff = (size_t)brow * F_DIM + bc * 8;

    /* ---- ldmatrix invariants ---- */
    const int l4   = lane >> 4;
    const int lk   = lane & 7;
    const int arw0 = wm * 64 + ((lane >> 3) & 1) * 8 + lk;
    const int bk0  = ((lane >> 3) & 1) * 8 + lk;
    const int ckey = tid & 7;                               /* convert swizzle key */

#define LOAD_STAGE(IT, SLOT)                                                   \
    {                                                                          \
        const uint32_t sa = sbase + (SLOT) * STAGE_BYTES + aoff;               \
        const float* ga = aG + (size_t)(IT) * KC + gaoff;                      \
        _Pragma("unroll")                                                      \
        for (int k = 0; k < 8; ++k)                                            \
            CPA16(sa + (uint32_t)k * 2048u, ga + (size_t)(16 * k) * L_DIM);    \
        const uint32_t sb = sbase + (SLOT) * STAGE_BYTES + A_STAGE + boff;     \
        const __half* gb = bG + (size_t)(IT) * KC * F_DIM + gboff;             \
        CPA16(sb,          gb);                                                \
        CPA16(sb + 2048u,  gb + 8 * F_DIM);                                    \
        CPA16(sb + 4096u,  gb + 16 * F_DIM);                                   \
        CPA16(sb + 6144u,  gb + 24 * F_DIM);                                   \
        asm volatile("cp.async.commit_group;");                                \
    }

/* in-place convert: thread owns row tid; fp32 chunks i at slot i^ckey; fp16 chunk c -> slot c^ckey */
#define CONVERT(SLOT)                                                          \
    {                                                                          \
        const uint32_t rb = sbase + (SLOT) * STAGE_BYTES + (uint32_t)tid * 128u;\
        _Pragma("unroll")                                                      \
        for (int cc = 0; cc < 4; ++cc) {                                       \
            float f0, f1, f2, f3, f4, f5, f6, f7;                              \
            asm volatile("ld.shared.v4.f32 {%0,%1,%2,%3},[%4];"                \
                : "=f"(f0), "=f"(f1), "=f"(f2), "=f"(f3)                       \
                : "r"(rb + (uint32_t)(((2 * cc) ^ ckey) << 4)));               \
            asm volatile("ld.shared.v4.f32 {%0,%1,%2,%3},[%4];"                \
                : "=f"(f4), "=f"(f5), "=f"(f6), "=f"(f7)                       \
                : "r"(rb + (uint32_t)(((2 * cc + 1) ^ ckey) << 4)));           \
            f0 = __expf(f0); f1 = __expf(f1); f2 = __expf(f2); f3 = __expf(f3);\
            f4 = __expf(f4); f5 = __expf(f5); f6 = __expf(f6); f7 = __expf(f7);\
            rsum += ((f0 + f1) + (f2 + f3)) + ((f4 + f5) + (f6 + f7));         \
            __half2 h0 = __floats2half2_rn(f0, f1);                            \
            __half2 h1 = __floats2half2_rn(f2, f3);                            \
            __half2 h2 = __floats2half2_rn(f4, f5);                            \
            __half2 h3 = __floats2half2_rn(f6, f7);                            \
            asm volatile("st.shared.v4.b32 [%0],{%1,%2,%3,%4};"                \
                :: "r"(rb + (uint32_t)((cc ^ ckey) << 4)),                     \
                   "r"(*(uint32_t*)&h0), "r"(*(uint32_t*)&h1),                 \
                   "r"(*(uint32_t*)&h2), "r"(*(uint32_t*)&h3) : "memory");     \
        }                                                                      \
    }

    float c[4][8][4];
    #pragma unroll
    for (int f = 0; f < 4; ++f)
        #pragma unroll
        for (int g = 0; g < 8; ++g)
            #pragma unroll
            for (int k = 0; k < 4; ++k) c[f][g][k] = 0.f;

    float rsum = 0.f;

    LOAD_STAGE(0, 0);
    LOAD_STAGE(1, 1);
    LOAD_STAGE(2, 2);

    asm volatile("cp.async.wait_group %0;" :: "n"(NSTAGE - 2));
    __syncthreads();
    CONVERT(0);

    int slot = 0, nslot = 3;
    for (int it = 0; it < NCH; ++it) {
        /* a: refill the ring (slot freed: fp16 of chunk it-1 read at iter it-1) */
        if (it + NSTAGE - 1 < NCH) {
            LOAD_STAGE(it + NSTAGE - 1, nslot);
        } else {
            asm volatile("cp.async.commit_group;");
        }

        /* b: conversions of chunk it visible to all warps */
        __syncthreads();

        /* c: fragments + unbroken MMA run for chunk it */
        const uint32_t Ab = sbase + slot * STAGE_BYTES;
        const uint32_t Bb = Ab + A_STAGE;

        uint32_t a[2][4][4];
        uint32_t bb[2][8][2];
        #pragma unroll
        for (int s = 0; s < 2; ++s) {
            #pragma unroll
            for (int f = 0; f < 4; ++f) {
                const uint32_t addr = Ab + (uint32_t)(arw0 + 16 * f) * 128u
                                    + (uint32_t)(((s * 2 + l4) ^ lk) << 4);
                LDSM4(a[s][f], addr);
            }
            #pragma unroll
            for (int j = 0; j < 4; ++j) {
                const int cidx = wn * 8 + j * 2 + l4;
                const uint32_t addr = Bb + (uint32_t)(s * 16 + bk0) * 256u
                                    + (uint32_t)(((cidx & 8) | ((cidx & 7) ^ lk)) << 4);
                uint32_t t0, t1, t2, t3;
                LDSM4T(t0, t1, t2, t3, addr);
                bb[s][2 * j][0] = t0;     bb[s][2 * j][1] = t1;
                bb[s][2 * j + 1][0] = t2; bb[s][2 * j + 1][1] = t3;
            }
        }
        #pragma unroll
        for (int s = 0; s < 2; ++s)
            #pragma unroll
            for (int f = 0; f < 4; ++f)
                #pragma unroll
                for (int g = 0; g < 8; ++g)
                    mma_f16(c[f][g], a[s][f], bb[s][g]);

        /* d: chunk it+1 fp32 data arrived */
        asm volatile("cp.async.wait_group %0;" :: "n"(NSTAGE - 2));
        __syncthreads();

        /* e: convert chunk it+1 (tensor pipe drains the MMA backlog meanwhile) */
        if (it + 1 < NCH) {
            const int cslot = (slot == NSTAGE - 1) ? 0 : slot + 1;
            CONVERT(cslot);
        }

        slot  = (slot == NSTAGE - 1) ? 0 : slot + 1;
        nslot = (nslot == NSTAGE - 1) ? 0 : nslot + 1;
    }

    /* ---- publish exact fp32 row sums (thread tid owns row tid) ---- */
    __syncthreads();
    float* Rs = (float*)smraw;          /* slot 0 region, no longer in use */
    Rs[tid] = rsum;
    __syncthreads();

    /* ---- epilogue: divide by rowsum, streaming store ---- */
    #pragma unroll
    for (int f = 0; f < 4; ++f) {
        const int r0 = wm * 64 + f * 16 + q;
        const int r1 = r0 + 8;
        const float inv0 = 1.0f / Rs[r0];
        const float inv1 = 1.0f / Rs[r1];
        #pragma unroll
        for (int g = 0; g < 8; ++g) {
            const int col = wn * 64 + g * 8 + 2 * qt;
            float2 lo, hi;
            lo.x = c[f][g][0] * inv0;
            lo.y = c[f][g][1] * inv0;
            hi.x = c[f][g][2] * inv1;
            hi.y = c[f][g][3] * inv1;
            __stcs((float2*)(oG + (size_t)r0 * F_DIM + col), lo);
            __stcs((float2*)(oG + (size_t)r1 * F_DIM + col), hi);
        }
    }
}

extern "C" void kernel_launch(void* const* d_in, const int* in_sizes, int n_in,
                              void* d_out, int out_size) {
    (void)in_sizes; (void)n_in; (void)out_size;
    const float* feature = (const float*)d_in[0];
    const float* noise   = (const float*)d_in[1];
    float* out = (float*)d_out;

    cudaFuncSetAttribute(FrameAugment_39771397161402_kernel,
                         cudaFuncAttributeMaxDynamicSharedMemorySize, SMEM_BYTES);

    prep_feat<<<(B_DIM * L_DIM * F_DIM) / (256 * 4), 256>>>(feature);

    dim3 grid(L_DIM / CTA_M, F_DIM / CTA_N, B_DIM);   /* 16 x 4 x 16 = 1024 CTAs */
    FrameAugment_39771397161402_kernel<<<grid, THREADS, SMEM_BYTES>>>(noise, out);
}